// round 17
// baseline (speedup 1.0000x reference)
#include <cuda_runtime.h>

#define B_   8
#define T_   2048
#define C_   192
#define TT   128
#define NBX  (T_ / TT)            // 16
#define RAD  8
#define NTAP (RAD + 1)
#define RING 17
#define ROWS_U 146                // u(t0-9 .. t0+136)
#define ROWS_G 130                // v(t0-1 .. t0+128)
#define NTH  960                  // 30 warps, 5 partitions of 192 channels
#define SMEM_BYTES ((ROWS_U + ROWS_G) * C_ * 4)   // 211,968 B -> 1 CTA/SM, 1 wave

#define GROUP_BAR(id) asm volatile("bar.sync %0, %1;" :: "r"(id), "r"(192) : "memory")

// ---------------------------------------------------------------------------
// Fused tile, TT=128, one CTA per SM, single wave (128 blocks), 30 warps.
// Thread = (channel c 0..191, partition tr 0..4). x streamed from global in
// batched 12-wide chunks; u and v staged in smem. Phases B/C/D are decoupled
// per partition via named group barriers; only A->B and D->E are CTA-wide.
// ---------------------------------------------------------------------------
template<bool EDGE>
__device__ __forceinline__ void run_tile(
    const float* __restrict__ xb,
    const float* __restrict__ dw, const float* __restrict__ db,
    const float* __restrict__ lw, const float* __restrict__ lb,
    const float* __restrict__ gamma, const float* __restrict__ beta,
    const float* __restrict__ ow, const float* __restrict__ ob,
    const float* __restrict__ kk,
    float* __restrict__ outb,
    float* us, float* vs, float* s_mu, float* s_rs, int t0)
{
    const int tid  = threadIdx.x;
    const int c    = tid % C_;
    const int tr   = tid / C_;     // 0..4
    const int lane = tid & 31;
    const int gw   = c >> 5;       // warp-in-group 0..5
    const int c2   = c >> 1;

    // ================= phase A: u build (x streamed, chunked loads) =========
    {
        const float dwu0 = dw[c2*3+0], dwu1 = dw[c2*3+1], dwu2 = dw[c2*3+2], dbu = db[c2];
        const float lwu0 = lw[c*3+0],  lwu1 = lw[c*3+1],  lwu2 = lw[c*3+2],  lbu = lb[c];
        const float* xc = xb + c2;

        const int i0a = tr * 30;                  // u rows [i0a, i0a+cnt)
        const int cnt = (tr < 4) ? 30 : 26;       // 4*30 + 26 = 146

        if (!EDGE) {
            const float g0 = lwu0*dwu0;
            const float g1 = lwu0*dwu1 + lwu1*dwu0;
            const float g2 = lwu0*dwu2 + lwu1*dwu1 + lwu2*dwu0;
            const float g3 = lwu1*dwu2 + lwu2*dwu1;
            const float g4 = lwu2*dwu2;
            const float gb = lbu + dbu*(lwu0 + lwu1 + lwu2);
#pragma unroll
            for (int q = 0; q < 4; q++) {
                const int tfirst = t0 - 9 + i0a + 8*q;
                float xv[12];
#pragma unroll
                for (int d = 0; d < 12; d++)
                    xv[d] = xc[(size_t)(tfirst - 2 + d) * C_];
#pragma unroll
                for (int j = 0; j < 8; j++) {
                    const int row = i0a + 8*q + j;
                    if (8*q + j < cnt) {
                        float p = gb + g0*xv[j] + g1*xv[j+1];
                        float r = g2*xv[j+2] + g3*xv[j+3] + g4*xv[j+4];
                        us[row*C_ + c] = p + r;
                    }
                }
            }
        } else {
#pragma unroll
            for (int q = 0; q < 4; q++) {
                const int tfirst = t0 - 9 + i0a + 8*q;
                float xv[12];
#pragma unroll
                for (int d = 0; d < 12; d++) {
                    const int tt = tfirst - 2 + d;
                    xv[d] = (tt >= 0 && tt < T_) ? xc[(size_t)tt * C_] : 0.f;
                }
#pragma unroll
                for (int j = 0; j < 8; j++) {
                    const int row = i0a + 8*q + j;
                    if (8*q + j < cnt) {
                        const int t = tfirst + j;
                        float h0 = dbu + dwu0*xv[j]   + dwu1*xv[j+1] + dwu2*xv[j+2];
                        float h1 = dbu + dwu0*xv[j+1] + dwu1*xv[j+2] + dwu2*xv[j+3];
                        float h2 = dbu + dwu0*xv[j+2] + dwu1*xv[j+3] + dwu2*xv[j+4];
                        if (t - 1 < 0)   h0 = 0.f;
                        if (t + 1 >= T_) h2 = 0.f;
                        float uv = lbu + lwu0*h0 + lwu1*h1 + lwu2*h2;
                        if (t < 0 || t >= T_) uv = 0.f;
                        us[row*C_ + c] = uv;
                    }
                }
            }
        }
    }
    __syncthreads();   // A -> B: u window spans partitions

    // ================= phase B: heat conv (ring) -> vs ======================
    {
        float f[NTAP];
        {
            const float kc = kk[c];
            const float amp = 0.5f * rsqrtf(3.14159265358979f * kc);
            const float inv = 0.25f / kc;
#pragma unroll
            for (int s = 0; s < NTAP; s++)
                f[s] = amp * __expf(-(float)(s*s) * inv);
        }

        const int i0 = tr * 26;                   // output rows [i0, i0+26)

        float w[RING];
#pragma unroll
        for (int q = 0; q < RING - 1; q++) w[q] = us[(i0+q)*C_ + c];
#pragma unroll
        for (int j = 0; j < 26; j++) {
            w[(RING-1+j) % RING] = us[(i0+j+RING-1)*C_ + c];
            float acc0 = f[0]*w[(j+8) % RING]
                       + f[3]*(w[(j+5) % RING] + w[(j+11) % RING])
                       + f[6]*(w[(j+2) % RING] + w[(j+14) % RING]);
            float acc1 = f[1]*(w[(j+7) % RING] + w[(j+9)  % RING])
                       + f[4]*(w[(j+4) % RING] + w[(j+12) % RING])
                       + f[7]*(w[(j+1) % RING] + w[(j+15) % RING]);
            float acc2 = f[2]*(w[(j+6) % RING] + w[(j+10) % RING])
                       + f[5]*(w[(j+3) % RING] + w[(j+13) % RING])
                       + f[8]*(w[(j+0) % RING] + w[(j+16) % RING]);
            vs[(i0+j)*C_ + c] = (acc0 + acc1) + acc2;
        }

        if (EDGE) {
            // mirror corrections (u outside [0,T) is zero-padded in us);
            // rows touched are within the owning partition (tr 0 / tr 4)
            if (t0 == 0 && tr == 0) {
#pragma unroll 1
                for (int i = 1; i <= 8; i++) {
                    const int t = i - 1;
                    float acc = 0.f;
#pragma unroll 1
                    for (int s = t + 1; s <= 8; s++)
                        acc += f[s] * us[(s - t + 8)*C_ + c];   // row = (s-t-1)+9
                    vs[i*C_ + c] += acc;
                }
            }
            if (t0 == T_ - TT && tr == 4) {
#pragma unroll 1
                for (int i = 121; i <= 128; i++) {
                    const int t = t0 - 1 + i;
                    float acc = 0.f;
#pragma unroll 1
                    for (int s = T_ - t; s <= 8; s++)
                        acc += f[s] * us[(4095 - t - s - t0 + 9)*C_ + c];
                    vs[i*C_ + c] += acc;
                }
            }
        }
    }
    GROUP_BAR(tr + 1);   // B -> C: stats only need own partition's vs rows

    // ================= phase C: LN stats (group-local, float2 loads) ========
    {
        const int i0 = tr * 26;
        for (int r = i0 + gw; r < i0 + 26; r += 6) {
            const float2* vp = (const float2*)(vs + r*C_);
            float s1 = 0.f, s2 = 0.f;
#pragma unroll
            for (int q = 0; q < 3; q++) {
                float2 vv = vp[lane + 32*q];
                s1 += vv.x + vv.y;
                s2 += vv.x*vv.x + vv.y*vv.y;
            }
#pragma unroll
            for (int m = 16; m; m >>= 1) {
                s1 += __shfl_xor_sync(0xffffffffu, s1, m);
                s2 += __shfl_xor_sync(0xffffffffu, s2, m);
            }
            if (lane == 0) {
                float mu  = s1 * (1.0f/C_);
                float var = s2 * (1.0f/C_) - mu*mu;
                s_mu[r] = mu;
                s_rs[r] = rsqrtf(var + 1e-5f);
            }
        }
    }
    GROUP_BAR(tr + 1);   // C -> D: gate needs own partition's stats only

    // ================= phase D: gate (LN apply + silu(z)), z streamed =======
    {
        const int zch = 96 + c2;
        const float dwz0 = dw[zch*3+0], dwz1 = dw[zch*3+1], dwz2 = dw[zch*3+2], dbz = db[zch];
        const float lwz0 = lw[(C_+c)*3+0], lwz1 = lw[(C_+c)*3+1], lwz2 = lw[(C_+c)*3+2], lbz = lb[C_+c];
        const float ga = gamma[c], be = beta[c];
        const float* xz = xb + zch;

        const int i0 = tr * 26;                   // rows [i0, i0+26)

        if (!EDGE) {
            const float z0 = lwz0*dwz0;
            const float z1 = lwz0*dwz1 + lwz1*dwz0;
            const float z2 = lwz0*dwz2 + lwz1*dwz1 + lwz2*dwz0;
            const float z3 = lwz1*dwz2 + lwz2*dwz1;
            const float z4 = lwz2*dwz2;
            const float zbias = lbz + dbz*(lwz0 + lwz1 + lwz2);
#pragma unroll
            for (int q = 0; q < 4; q++) {
                const int tfirst = t0 - 1 + i0 + 8*q;
                float xv[12];
#pragma unroll
                for (int d = 0; d < 12; d++)
                    xv[d] = xz[(size_t)(tfirst - 2 + d) * C_];
#pragma unroll
                for (int j = 0; j < 8; j++) {
                    const int row = i0 + 8*q + j;
                    if (8*q + j < 26) {
                        float p  = zbias + z0*xv[j] + z1*xv[j+1];
                        float r  = z2*xv[j+2] + z3*xv[j+3] + z4*xv[j+4];
                        float zv = p + r;
                        float v = vs[row*C_ + c];
                        float g = (v - s_mu[row]) * s_rs[row] * ga + be;
                        g *= zv * (1.0f / (1.0f + __expf(-zv)));
                        vs[row*C_ + c] = g;
                    }
                }
            }
        } else {
#pragma unroll
            for (int q = 0; q < 4; q++) {
                const int tfirst = t0 - 1 + i0 + 8*q;
                float xv[12];
#pragma unroll
                for (int d = 0; d < 12; d++) {
                    const int tt = tfirst - 2 + d;
                    xv[d] = (tt >= 0 && tt < T_) ? xz[(size_t)tt * C_] : 0.f;
                }
#pragma unroll
                for (int j = 0; j < 8; j++) {
                    const int row = i0 + 8*q + j;
                    if (8*q + j < 26) {
                        const int t = tfirst + j;
                        float h0 = dbz + dwz0*xv[j]   + dwz1*xv[j+1] + dwz2*xv[j+2];
                        float h1 = dbz + dwz0*xv[j+1] + dwz1*xv[j+2] + dwz2*xv[j+3];
                        float h2 = dbz + dwz0*xv[j+2] + dwz1*xv[j+3] + dwz2*xv[j+4];
                        if (t - 1 < 0)   h0 = 0.f;
                        if (t + 1 >= T_) h2 = 0.f;
                        float zv = lbz + lwz0*h0 + lwz1*h1 + lwz2*h2;
                        float v = vs[row*C_ + c];
                        float g = (v - s_mu[row]) * s_rs[row] * ga + be;
                        g *= zv * (1.0f / (1.0f + __expf(-zv)));
                        if (t < 0 || t >= T_) g = 0.f;
                        vs[row*C_ + c] = g;
                    }
                }
            }
        }
    }
    __syncthreads();   // D -> E: final conv reads across partition boundaries

    // ================= phase E: final conv3 + store =========================
    {
        const float ow0 = ow[c*3+0], ow1 = ow[c*3+1], ow2 = ow[c*3+2], obc = ob[c];
        const int i0e = tr * 26;                  // output rows [i0e, i0e+cnt)
        const int cnt = (tr < 4) ? 26 : 24;       // 4*26 + 24 = 128
        float g0 = vs[(i0e+0)*C_ + c];
        float g1 = vs[(i0e+1)*C_ + c];
#pragma unroll
        for (int j = 0; j < 26; j++) {
            if (j < cnt) {
                float g2 = vs[(i0e+j+2)*C_ + c];
                outb[(size_t)(t0 + i0e + j)*C_ + c] = obc + ow0*g0 + ow1*g1 + ow2*g2;
                g0 = g1; g1 = g2;
            }
        }
    }
}

// ---------------------------------------------------------------------------
__global__ __launch_bounds__(NTH, 1)
void fused_kernel(const float* __restrict__ x,
                  const float* __restrict__ dw, const float* __restrict__ db,
                  const float* __restrict__ lw, const float* __restrict__ lb,
                  const float* __restrict__ gamma, const float* __restrict__ beta,
                  const float* __restrict__ ow, const float* __restrict__ ob,
                  const float* __restrict__ kk,
                  float* __restrict__ out)
{
    extern __shared__ float sm[];
    float* us = sm;
    float* vs = sm + ROWS_U * C_;
    __shared__ float s_mu[ROWS_G], s_rs[ROWS_G];

    const int b  = blockIdx.y;
    const int bx = blockIdx.x;
    const int t0 = bx * TT;
    const float* xb   = x   + (size_t)b * T_ * C_;
    float*       outb = out + (size_t)b * T_ * C_;

    if (bx == 0 || bx == NBX - 1)
        run_tile<true >(xb, dw, db, lw, lb, gamma, beta, ow, ob, kk, outb,
                        us, vs, s_mu, s_rs, t0);
    else
        run_tile<false>(xb, dw, db, lw, lb, gamma, beta, ow, ob, kk, outb,
                        us, vs, s_mu, s_rs, t0);
}

// ---------------------------------------------------------------------------
extern "C" void kernel_launch(void* const* d_in, const int* in_sizes, int n_in,
                              void* d_out, int out_size)
{
    const float* x  = (const float*)d_in[0];
    const float* dw = (const float*)d_in[1];
    const float* db = (const float*)d_in[2];
    const float* lw = (const float*)d_in[3];
    const float* lb = (const float*)d_in[4];
    const float* ga = (const float*)d_in[5];
    const float* be = (const float*)d_in[6];
    const float* ow = (const float*)d_in[7];
    const float* ob = (const float*)d_in[8];
    const float* k  = (const float*)d_in[9];
    float* out = (float*)d_out;

    cudaFuncSetAttribute(fused_kernel, cudaFuncAttributeMaxDynamicSharedMemorySize,
                         SMEM_BYTES);

    fused_kernel<<<dim3(NBX, B_), NTH, SMEM_BYTES>>>(x, dw, db, lw, lb,
                                                     ga, be, ow, ob, k, out);
}